// round 15
// baseline (speedup 1.0000x reference)
#include <cuda_runtime.h>

#define BB 8
#define HH 512
#define WW 512
#define BIGF 1.0e6f
#define BIG2 1.0e12f
#define NPIX (BB * HH * WW)          // 2097152
#define NGRP  16
#define KW    (HH / 32)              // 16 word-rows
#define TILE  128                    // interior columns per block
#define NT    (WW / TILE)            // 4 tiles per row-band
#define TPB   256
#define MAIN_GRID (NGRP * KW * NT)   // 1024
#define SROW  136                    // 128 interior + 2*4 halo

__device__ unsigned g_cbits[NGRP * KW * WW];   // column-packed fg bits, 512 KB
__device__ float    g_blksum[MAIN_GRID];
__device__ unsigned g_maxbits[NGRP];
__device__ unsigned g_counter = 0;

__device__ __forceinline__ float redux_max_f32nn(float v) {
    unsigned r;
    asm("redux.sync.max.u32 %0, %1, 0xffffffff;" : "=r"(r) : "r"(__float_as_uint(v)));
    return __uint_as_float(r);
}

// Pass 1: pack masks into column words, vec4 I/O (measured ~1.5us).
__global__ void k_bits(const float* __restrict__ out, const int* __restrict__ tgt) {
    __shared__ uint4 sh[128];
    int bi = blockIdx.x;              // [mb][hc] : 256 blocks
    if (bi == 0 && threadIdx.x < NGRP) g_maxbits[threadIdx.x] = 0u;

    int hc = bi & (KW - 1);
    int mb = bi >> 4;
    int m = mb >> 3, b = mb & 7;
    int vw   = threadIdx.x & 127;
    int half = threadIdx.x >> 7;
    int w  = vw << 2;
    int h0 = (hc << 5) + (half << 4);

    unsigned w0 = 0, w1 = 0, w2 = 0, w3 = 0;
    if (m == 0) {
        const int4* p = (const int4*)(tgt + (size_t)(b * HH + h0) * WW + w);
        #pragma unroll
        for (int hh = 0; hh < 16; ++hh) {
            int4 v = p[hh * (WW / 4)];
            unsigned s = (unsigned)((half << 4) + hh);
            w0 |= (unsigned)(v.x > 0) << s;  w1 |= (unsigned)(v.y > 0) << s;
            w2 |= (unsigned)(v.z > 0) << s;  w3 |= (unsigned)(v.w > 0) << s;
        }
    } else {
        const float4* p = (const float4*)(out + (size_t)((b * 2 + 1) * HH + h0) * WW + w);
        #pragma unroll
        for (int hh = 0; hh < 16; ++hh) {
            float4 v = p[hh * (WW / 4)];
            unsigned s = (unsigned)((half << 4) + hh);
            w0 |= (unsigned)(v.x > 0.5f) << s;  w1 |= (unsigned)(v.y > 0.5f) << s;
            w2 |= (unsigned)(v.z > 0.5f) << s;  w3 |= (unsigned)(v.w > 0.5f) << s;
        }
    }
    if (half == 0) sh[vw] = make_uint4(w0, w1, w2, w3);
    __syncthreads();
    if (half == 1) {
        uint4 o4 = sh[vw];
        ((uint4*)(g_cbits + (size_t)(mb * KW + hc) * WW))[vw] =
            make_uint4(w0 | o4.x, w1 | o4.y, w2 | o4.z, w3 | o4.w);
    }
}

// Fully general vertical distance (word-walk). Rare path / fallback helper.
__device__ __noinline__ float vdist_slow(const unsigned* __restrict__ cb,
                                         unsigned c, int h, int k, unsigned o, int j) {
    float u;
    unsigned inv = ~c & ((o == 0) ? 0u : ((1u << o) - 1u));
    if (inv) {
        u = (float)((int)o - (31 - __clz(inv)));
    } else {
        int kk = k - 1; unsigned iv = 0;
        while (kk >= 0 && !(iv = ~cb[kk * WW + j])) --kk;
        u = (kk >= 0) ? (float)(h - (kk * 32 + 31 - __clz(iv)))
                      : (BIGF + (float)(h + 1));
    }
    float dn;
    unsigned inv2 = ~c & (0xFFFFFFFEu << o);
    if (inv2) {
        dn = (float)((__ffs(inv2) - 1) - (int)o);
    } else {
        int kk = k + 1; unsigned iv = 0;
        while (kk < KW && !(iv = ~cb[kk * WW + j])) ++kk;
        dn = (kk < KW) ? (float)(kk * 32 + __ffs(iv) - 1 - h)
                       : (BIGF + (float)(HH - h));
    }
    return fminf(u, dn);
}

// general g^2 at (h, col j) recomputed from global bits (exact).
__device__ float vdist2_g(const unsigned* __restrict__ cb, int h, int j) {
    int k = h >> 5; unsigned o = (unsigned)(h & 31);
    unsigned c = cb[k * WW + j];
    if (!((c >> o) & 1u)) return 0.0f;
    float g = vdist_slow(cb, c, h, k, o, j);
    return g * g;
}

// single-pixel vdist (halo columns): windowed u64 version.
__device__ __forceinline__ float vdist1(const unsigned* __restrict__ cb, unsigned c,
                                        unsigned cu, unsigned cd,
                                        int k, int o, int gc) {
    if (!((c >> o) & 1u)) return 0.0f;
    unsigned long long nu = ~((((unsigned long long)c)  << 32) | (unsigned long long)cu);
    unsigned long long nd = ~((((unsigned long long)cd) << 32) | (unsigned long long)c);
    unsigned long long mku = (o == 31) ? 0x7FFFFFFFFFFFFFFFULL
                                       : ((1ULL << (32 + o)) - 1ULL);
    unsigned long long mkd = 0xFFFFFFFFFFFFFFFEULL << o;
    unsigned long long mu = nu & mku;
    unsigned long long md = nd & mkd;
    if (mu && md) {
        int iu = (32 + o) - (63 - __clzll((long long)mu));
        int id = __ffsll((long long)md) - 1 - o;
        int gi = min(iu, id);
        return (float)(gi * gi);
    }
    float g = vdist_slow(cb, c, (k << 5) + o, k, (unsigned)o, gc);  // rare
    return g * g;
}

// Exact fallback for r>=5 for 8 pixels (p ~ 2^-54/pixel).
__device__ __noinline__ void env_fallback8(const unsigned* __restrict__ cb,
                                           int h, int gc0, float* best) {
    #pragma unroll
    for (int i = 0; i < 8; ++i) {
        float bb = best[i];
        if (bb > 25.0f) {
            int p = gc0 + i;
            for (int r = 5; r < WW; ++r) {
                float rr = (float)(r * r);            // integer-exact in fp32
                if (rr >= bb) break;                  // rigorous exact cutoff
                if (p - r >= 0) bb = fminf(bb, vdist2_g(cb, h, p - r) + rr);
                if (p + r < WW) bb = fminf(bb, vdist2_g(cb, h, p + r) + rr);
            }
            best[i] = bb;
        }
    }
}

// Pass 2: band block = 32 rows x 128 cols (+8 halo), one mask, 256 threads;
// 7 blocks/SM forced -> single wave (1036 >= 1024). Last block finalizes.
__global__ void __launch_bounds__(TPB, 7)
k_band(const float* __restrict__ out, float* __restrict__ res) {
    __shared__ __align__(16) float s[32][SROW];
    __shared__ float red[2][8];
    __shared__ double part[16];
    __shared__ bool amLast;

    int t = threadIdx.x;
    int bi = blockIdx.x;                 // [mb][k][tile]
    int tile0 = (bi & (NT - 1)) * TILE;
    int k  = (bi >> 2) & (KW - 1);
    int mb = bi >> 6;
    int b = mb & 7;

    const unsigned* cb = g_cbits + (size_t)mb * KW * WW;

    // ---- phase 1a: vdist via u32 zero-position scans, 16 bits/thread ----
    {
        int col = t & 127;
        int o0  = (t >> 7) << 4;          // 0 or 16
        int gc  = tile0 + col;
        unsigned c  = cb[k * WW + gc];
        unsigned cu = (k > 0)      ? cb[(k - 1) * WW + gc] : 0xFFFFFFFFu;
        unsigned cd = (k < KW - 1) ? cb[(k + 1) * WW + gc] : 0xFFFFFFFFu;

        // backward scan: down-distance per bit, packed 8 bits each
        int nzp;                           // next-zero h-coord above current o
        {
            unsigned above = (o0 == 0) ? (~c & 0xFFFF0000u) : 0u;
            if (above)    nzp = __ffs(above) - 1;
            else if (~cd) nzp = 32 + __ffs(~cd) - 1;
            else          nzp = 1000;      // sentinel: no zero in window
        }
        unsigned long long pk0 = 0ULL, pk1 = 0ULL;
        #pragma unroll
        for (int q = 15; q >= 0; --q) {
            int o = o0 + q;
            int dn;
            if (!((c >> o) & 1u)) { nzp = o; dn = 0; }
            else dn = nzp - o;
            unsigned dn8 = (unsigned)min(dn, 255);
            if (q < 8) pk0 |= (unsigned long long)dn8 << (q * 8);
            else       pk1 |= (unsigned long long)dn8 << ((q - 8) * 8);
        }

        // forward scan: up-distance, combine, store g^2
        int lzp;                           // last-zero h-coord below current o
        {
            unsigned below = (o0 == 0) ? 0u : (~c & 0xFFFFu);
            if (below)    lzp = 31 - __clz(below);
            else if (~cu) lzp = -1 - __clz(~cu);
            else          lzp = -1000;     // sentinel
        }
        float* sp = &s[o0][col + 4];
        #pragma unroll
        for (int q = 0; q < 16; ++q) {
            int o = o0 + q;
            float gsq;
            if (!((c >> o) & 1u)) {
                lzp = o; gsq = 0.0f;
            } else {
                int up = o - lzp;
                int dn = (int)((q < 8 ? (pk0 >> (q * 8)) : (pk1 >> ((q - 8) * 8))) & 0xFFULL);
                int g = min(up, dn);
                if (g > 31) {              // rare: window escape / boundary
                    float gs = vdist_slow(cb, c, (k << 5) + o, k, (unsigned)o, gc);
                    gsq = gs * gs;
                } else {
                    gsq = (float)(g * g);  // exact: off-window side >= 33 > 31
                }
            }
            *sp = gsq;
            sp += SROW;
        }
    }
    // ---- phase 1b: halo columns (8 cols x 32 rows, 1 px/thread) ----
    {
        int ci = t >> 5;                  // 0..7
        int o  = t & 31;
        int sidx = (ci < 4) ? ci : (132 + (ci - 4));
        int gc   = (ci < 4) ? (tile0 - 4 + ci) : (tile0 + 124 + ci);
        if (gc < 0 || gc >= WW) {
            s[o][sidx] = BIG2;
        } else {
            unsigned c  = cb[k * WW + gc];
            unsigned cu = (k > 0)      ? cb[(k - 1) * WW + gc] : 0xFFFFFFFFu;
            unsigned cd = (k < KW - 1) ? cb[(k + 1) * WW + gc] : 0xFFFFFFFFu;
            s[o][sidx] = vdist1(cb, c, cu, cd, k, o, gc);
        }
    }
    __syncthreads();

    // ---- phase 2: envelope + loss; warp = 2 rows x (16 lanes x 8 px) ----
    int w  = t >> 5;                      // warp 0..7
    int tc = t & 31;
    int hl = tc >> 4;                     // row half 0/1
    int l  = tc & 15;
    int c0 = l << 3;                      // interior col offset (0..120)

    float vacc = 0.0f, macc = 0.0f;
    #pragma unroll
    for (int it = 0; it < 2; ++it) {
        int r = (it << 4) + (w << 1) + hl;           // row 0..31
        const float4* wp = (const float4*)&s[r][c0]; // 16B aligned
        float4 A0 = wp[0], A1 = wp[1], A2 = wp[2], A3 = wp[3];
        float W[16] = {A0.x, A0.y, A0.z, A0.w, A1.x, A1.y, A1.z, A1.w,
                       A2.x, A2.y, A2.z, A2.w, A3.x, A3.y, A3.z, A3.w};
        float best[8];
        float rowmax = 0.0f;
        #pragma unroll
        for (int i = 0; i < 8; ++i) {
            // min-then-add: exact (fp32 add is monotone, same constant)
            float bb = fminf(W[i + 4], BIG2);        // best0 = BIG*BIG clamp
            float c1 = fminf(W[i + 3], W[i + 5]) + 1.0f;
            float c2 = fminf(W[i + 2], W[i + 6]) + 4.0f;
            float c3 = fminf(W[i + 1], W[i + 7]) + 9.0f;
            float c4 = fminf(W[i],     W[i + 8]) + 16.0f;
            bb = fminf(fminf(bb, c1), fminf(fminf(c2, c3), c4));
            best[i] = bb;
            rowmax = fmaxf(rowmax, bb);
        }
        if (rowmax > 25.0f)                           // essentially never
            env_fallback8(cb, (k << 5) + r, tile0 + c0, best);
        macc = fmaxf(macc, rowmax);

        // gt words loaded per-iteration (short live range, L1-hit)
        const unsigned* gp = g_cbits + (size_t)b * KW * WW + k * WW + tile0 + c0;
        uint4 gwa = *(const uint4*)gp;
        uint4 gwb = *(const uint4*)(gp + 4);
        unsigned gw[8] = {gwa.x, gwa.y, gwa.z, gwa.w, gwb.x, gwb.y, gwb.z, gwb.w};

        const float* op = out + ((size_t)((b * 2 + 1) * HH + (k << 5) + r)) * WW
                              + tile0 + c0;
        float4 s0 = *(const float4*)op;
        float4 s1 = *(const float4*)(op + 4);
        float sv[8] = {s0.x, s0.y, s0.z, s0.w, s1.x, s1.y, s1.z, s1.w};
        #pragma unroll
        for (int i = 0; i < 8; ++i) {
            float gtv = (float)((gw[i] >> r) & 1u);   // gt float == gt bit
            float d = sv[i] - gtv;
            vacc += d * d * best[i];
        }
    }

    // ---- block reduce (8 warps) ----
    #pragma unroll
    for (int ofs = 16; ofs > 0; ofs >>= 1)
        vacc += __shfl_xor_sync(0xffffffffu, vacc, ofs);
    macc = redux_max_f32nn(macc);
    if (tc == 0) { red[0][w] = vacc; red[1][w] = macc; }
    __syncthreads();
    if (t == 0) {
        float x = ((red[0][0] + red[0][1]) + (red[0][2] + red[0][3]))
                + ((red[0][4] + red[0][5]) + (red[0][6] + red[0][7]));
        float y = fmaxf(fmaxf(fmaxf(red[1][0], red[1][1]), fmaxf(red[1][2], red[1][3])),
                        fmaxf(fmaxf(red[1][4], red[1][5]), fmaxf(red[1][6], red[1][7])));
        g_blksum[bi] = x;
        atomicMax(&g_maxbits[mb], __float_as_uint(y));
    }

    // ---- last-block finalize ----
    __threadfence();
    if (t == 0) amLast = (atomicAdd(&g_counter, 1u) == MAIN_GRID - 1);
    __syncthreads();
    if (!amLast) return;

    if (t < 128) {
        int wq = t >> 5, lq = t & 31;     // 4 warps x 4 groups each
        #pragma unroll
        for (int q = 0; q < 4; ++q) {
            int g = (wq << 2) + q;        // group = mb; 64 partials each
            double acc = (double)g_blksum[g * 64 + lq] + (double)g_blksum[g * 64 + 32 + lq];
            #pragma unroll
            for (int ofs = 16; ofs > 0; ofs >>= 1)
                acc += __shfl_xor_sync(0xffffffffu, acc, ofs);
            if (lq == 0) {
                double mx = (double)fmaxf(__uint_as_float(g_maxbits[g]), 1.0f);
                part[g] = acc / mx;
            }
        }
    }
    __syncthreads();
    if (t == 0) {
        double total = 0.0;
        #pragma unroll
        for (int q = 0; q < 16; ++q) total += part[q];
        res[0] = (float)(total * (1.0 / (double)NPIX));
        g_counter = 0;                    // reset for next replay
    }
}

extern "C" void kernel_launch(void* const* d_in, const int* in_sizes, int n_in,
                              void* d_out, int out_size) {
    const float* out = (const float*)d_in[0];   // [8,2,512,512] float32
    const int*   tgt = (const int*)d_in[1];     // [8,1,512,512] int32

    k_bits<<<NGRP * KW, 256>>>(out, tgt);       // 256 blocks
    k_band<<<MAIN_GRID, TPB>>>(out, (float*)d_out);
}

// round 16
// speedup vs baseline: 1.0626x; 1.0626x over previous
#include <cuda_runtime.h>

#define BB 8
#define HH 512
#define WW 512
#define BIGF 1.0e6f
#define BIG2 1.0e12f
#define NPIX (BB * HH * WW)          // 2097152
#define NGRP  16
#define KW    (HH / 32)              // 16 word-rows
#define TILE  128                    // interior columns per tile
#define TPB   256
#define NBLK  512                    // blocks; each handles 2 adjacent tiles
#define SROW  136                    // 128 interior + 2*4 halo

__device__ unsigned g_cbits[NGRP * KW * WW];   // column-packed fg bits, 512 KB
__device__ float    g_blksum[NBLK];
__device__ unsigned g_maxbits[NGRP];
__device__ unsigned g_counter = 0;

__device__ __forceinline__ float redux_max_f32nn(float v) {
    unsigned r;
    asm("redux.sync.max.u32 %0, %1, 0xffffffff;" : "=r"(r) : "r"(__float_as_uint(v)));
    return __uint_as_float(r);
}

// Pass 1: pack masks into column words, vec4 I/O (measured ~1.5us).
__global__ void k_bits(const float* __restrict__ out, const int* __restrict__ tgt) {
    __shared__ uint4 sh[128];
    int bi = blockIdx.x;              // [mb][hc] : 256 blocks
    if (bi == 0 && threadIdx.x < NGRP) g_maxbits[threadIdx.x] = 0u;

    int hc = bi & (KW - 1);
    int mb = bi >> 4;
    int m = mb >> 3, b = mb & 7;
    int vw   = threadIdx.x & 127;
    int half = threadIdx.x >> 7;
    int w  = vw << 2;
    int h0 = (hc << 5) + (half << 4);

    unsigned w0 = 0, w1 = 0, w2 = 0, w3 = 0;
    if (m == 0) {
        const int4* p = (const int4*)(tgt + (size_t)(b * HH + h0) * WW + w);
        #pragma unroll
        for (int hh = 0; hh < 16; ++hh) {
            int4 v = p[hh * (WW / 4)];
            unsigned s = (unsigned)((half << 4) + hh);
            w0 |= (unsigned)(v.x > 0) << s;  w1 |= (unsigned)(v.y > 0) << s;
            w2 |= (unsigned)(v.z > 0) << s;  w3 |= (unsigned)(v.w > 0) << s;
        }
    } else {
        const float4* p = (const float4*)(out + (size_t)((b * 2 + 1) * HH + h0) * WW + w);
        #pragma unroll
        for (int hh = 0; hh < 16; ++hh) {
            float4 v = p[hh * (WW / 4)];
            unsigned s = (unsigned)((half << 4) + hh);
            w0 |= (unsigned)(v.x > 0.5f) << s;  w1 |= (unsigned)(v.y > 0.5f) << s;
            w2 |= (unsigned)(v.z > 0.5f) << s;  w3 |= (unsigned)(v.w > 0.5f) << s;
        }
    }
    if (half == 0) sh[vw] = make_uint4(w0, w1, w2, w3);
    __syncthreads();
    if (half == 1) {
        uint4 o4 = sh[vw];
        ((uint4*)(g_cbits + (size_t)(mb * KW + hc) * WW))[vw] =
            make_uint4(w0 | o4.x, w1 | o4.y, w2 | o4.z, w3 | o4.w);
    }
}

// Fully general vertical distance (word-walk). Rare path / fallback helper.
__device__ __noinline__ float vdist_slow(const unsigned* __restrict__ cb,
                                         unsigned c, int h, int k, unsigned o, int j) {
    float u;
    unsigned inv = ~c & ((o == 0) ? 0u : ((1u << o) - 1u));
    if (inv) {
        u = (float)((int)o - (31 - __clz(inv)));
    } else {
        int kk = k - 1; unsigned iv = 0;
        while (kk >= 0 && !(iv = ~cb[kk * WW + j])) --kk;
        u = (kk >= 0) ? (float)(h - (kk * 32 + 31 - __clz(iv)))
                      : (BIGF + (float)(h + 1));
    }
    float dn;
    unsigned inv2 = ~c & (0xFFFFFFFEu << o);
    if (inv2) {
        dn = (float)((__ffs(inv2) - 1) - (int)o);
    } else {
        int kk = k + 1; unsigned iv = 0;
        while (kk < KW && !(iv = ~cb[kk * WW + j])) ++kk;
        dn = (kk < KW) ? (float)(kk * 32 + __ffs(iv) - 1 - h)
                       : (BIGF + (float)(HH - h));
    }
    return fminf(u, dn);
}

// general g^2 at (h, col j) recomputed from global bits (exact).
__device__ float vdist2_g(const unsigned* __restrict__ cb, int h, int j) {
    int k = h >> 5; unsigned o = (unsigned)(h & 31);
    unsigned c = cb[k * WW + j];
    if (!((c >> o) & 1u)) return 0.0f;
    float g = vdist_slow(cb, c, h, k, o, j);
    return g * g;
}

// single-pixel vdist (halo columns): windowed u64 version.
__device__ __forceinline__ float vdist1(const unsigned* __restrict__ cb, unsigned c,
                                        unsigned cu, unsigned cd,
                                        int k, int o, int gc) {
    if (!((c >> o) & 1u)) return 0.0f;
    unsigned long long nu = ~((((unsigned long long)c)  << 32) | (unsigned long long)cu);
    unsigned long long nd = ~((((unsigned long long)cd) << 32) | (unsigned long long)c);
    unsigned long long mku = (o == 31) ? 0x7FFFFFFFFFFFFFFFULL
                                       : ((1ULL << (32 + o)) - 1ULL);
    unsigned long long mkd = 0xFFFFFFFFFFFFFFFEULL << o;
    unsigned long long mu = nu & mku;
    unsigned long long md = nd & mkd;
    if (mu && md) {
        int iu = (32 + o) - (63 - __clzll((long long)mu));
        int id = __ffsll((long long)md) - 1 - o;
        int gi = min(iu, id);
        return (float)(gi * gi);
    }
    float g = vdist_slow(cb, c, (k << 5) + o, k, (unsigned)o, gc);  // rare
    return g * g;
}

// Exact fallback for r>=5 for 8 pixels (p ~ 2^-54/pixel).
__device__ __noinline__ void env_fallback8(const unsigned* __restrict__ cb,
                                           int h, int gc0, float* best) {
    #pragma unroll
    for (int i = 0; i < 8; ++i) {
        float bb = best[i];
        if (bb > 25.0f) {
            int p = gc0 + i;
            for (int r = 5; r < WW; ++r) {
                float rr = (float)(r * r);            // integer-exact in fp32
                if (rr >= bb) break;                  // rigorous exact cutoff
                if (p - r >= 0) bb = fminf(bb, vdist2_g(cb, h, p - r) + rr);
                if (p + r < WW) bb = fminf(bb, vdist2_g(cb, h, p + r) + rr);
            }
            best[i] = bb;
        }
    }
}

// Pass 2: block handles TWO adjacent 32x128 tiles of one (mask,batch,k) band.
// 512 blocks, single wave at 48 regs (740 slots). Last block finalizes.
__global__ void __launch_bounds__(TPB)
k_band(const float* __restrict__ out, float* __restrict__ res) {
    __shared__ __align__(16) float s[32][SROW];
    __shared__ float red[2][8];
    __shared__ double part[16];
    __shared__ bool amLast;

    int t = threadIdx.x;
    int bi = blockIdx.x;                 // [mb][k][pair]
    int pair = bi & 1;
    int k  = (bi >> 1) & (KW - 1);
    int mb = bi >> 5;
    int b = mb & 7;

    const unsigned* cb = g_cbits + (size_t)mb * KW * WW;

    float vacc = 0.0f, macc = 0.0f;

    #pragma unroll 1
    for (int sub = 0; sub < 2; ++sub) {
        int tile0 = ((pair << 1) + sub) * TILE;

        // ---- phase 1a: vdist via u32 zero-position scans, 16 bits/thread ----
        {
            int col = t & 127;
            int o0  = (t >> 7) << 4;          // 0 or 16
            int gc  = tile0 + col;
            unsigned c  = cb[k * WW + gc];
            unsigned cu = (k > 0)      ? cb[(k - 1) * WW + gc] : 0xFFFFFFFFu;
            unsigned cd = (k < KW - 1) ? cb[(k + 1) * WW + gc] : 0xFFFFFFFFu;

            // backward scan: down-distance per bit, packed 8 bits each
            int nzp;                           // next-zero h-coord above current o
            {
                unsigned above = (o0 == 0) ? (~c & 0xFFFF0000u) : 0u;
                if (above)    nzp = __ffs(above) - 1;
                else if (~cd) nzp = 32 + __ffs(~cd) - 1;
                else          nzp = 1000;      // sentinel: no zero in window
            }
            unsigned long long pk0 = 0ULL, pk1 = 0ULL;
            #pragma unroll
            for (int q = 15; q >= 0; --q) {
                int o = o0 + q;
                int dn;
                if (!((c >> o) & 1u)) { nzp = o; dn = 0; }
                else dn = nzp - o;
                unsigned dn8 = (unsigned)min(dn, 255);
                if (q < 8) pk0 |= (unsigned long long)dn8 << (q * 8);
                else       pk1 |= (unsigned long long)dn8 << ((q - 8) * 8);
            }

            // forward scan: up-distance, combine, store g^2
            int lzp;                           // last-zero h-coord below current o
            {
                unsigned below = (o0 == 0) ? 0u : (~c & 0xFFFFu);
                if (below)    lzp = 31 - __clz(below);
                else if (~cu) lzp = -1 - __clz(~cu);
                else          lzp = -1000;     // sentinel
            }
            float* sp = &s[o0][(t & 127) + 4];
            #pragma unroll
            for (int q = 0; q < 16; ++q) {
                int o = o0 + q;
                float gsq;
                if (!((c >> o) & 1u)) {
                    lzp = o; gsq = 0.0f;
                } else {
                    int up = o - lzp;
                    int dn = (int)((q < 8 ? (pk0 >> (q * 8)) : (pk1 >> ((q - 8) * 8))) & 0xFFULL);
                    int g = min(up, dn);
                    if (g > 31) {              // rare: window escape / boundary
                        float gs = vdist_slow(cb, c, (k << 5) + o, k, (unsigned)o, gc);
                        gsq = gs * gs;
                    } else {
                        gsq = (float)(g * g);  // exact: off-window side >= 33 > 31
                    }
                }
                *sp = gsq;
                sp += SROW;
            }
        }
        // ---- phase 1b: halo columns (8 cols x 32 rows, 1 px/thread) ----
        {
            int ci = t >> 5;                  // 0..7
            int o  = t & 31;
            int sidx = (ci < 4) ? ci : (132 + (ci - 4));
            int gc   = (ci < 4) ? (tile0 - 4 + ci) : (tile0 + 124 + ci);
            if (gc < 0 || gc >= WW) {
                s[o][sidx] = BIG2;
            } else {
                unsigned c  = cb[k * WW + gc];
                unsigned cu = (k > 0)      ? cb[(k - 1) * WW + gc] : 0xFFFFFFFFu;
                unsigned cd = (k < KW - 1) ? cb[(k + 1) * WW + gc] : 0xFFFFFFFFu;
                s[o][sidx] = vdist1(cb, c, cu, cd, k, o, gc);
            }
        }
        __syncthreads();

        // ---- phase 2: envelope + loss; warp = 2 rows x (16 lanes x 8 px) ----
        int w  = t >> 5;                      // warp 0..7
        int tc = t & 31;
        int hl = tc >> 4;                     // row half 0/1
        int l  = tc & 15;
        int c0 = l << 3;                      // interior col offset (0..120)

        const unsigned* gp0 = g_cbits + (size_t)b * KW * WW + k * WW + tile0 + c0;
        uint4 gwa = *(const uint4*)gp0;
        uint4 gwb = *(const uint4*)(gp0 + 4);
        unsigned gw[8] = {gwa.x, gwa.y, gwa.z, gwa.w, gwb.x, gwb.y, gwb.z, gwb.w};

        #pragma unroll
        for (int it = 0; it < 2; ++it) {
            int r = (it << 4) + (w << 1) + hl;           // row 0..31
            const float4* wp = (const float4*)&s[r][c0]; // 16B aligned
            float4 A0 = wp[0], A1 = wp[1], A2 = wp[2], A3 = wp[3];
            float W[16] = {A0.x, A0.y, A0.z, A0.w, A1.x, A1.y, A1.z, A1.w,
                           A2.x, A2.y, A2.z, A2.w, A3.x, A3.y, A3.z, A3.w};
            float best[8];
            float rowmax = 0.0f;
            #pragma unroll
            for (int i = 0; i < 8; ++i) {
                // min-then-add: exact (fp32 add is monotone, same constant)
                float bb = fminf(W[i + 4], BIG2);        // best0 = BIG*BIG clamp
                float c1 = fminf(W[i + 3], W[i + 5]) + 1.0f;
                float c2 = fminf(W[i + 2], W[i + 6]) + 4.0f;
                float c3 = fminf(W[i + 1], W[i + 7]) + 9.0f;
                float c4 = fminf(W[i],     W[i + 8]) + 16.0f;
                bb = fminf(fminf(bb, c1), fminf(fminf(c2, c3), c4));
                best[i] = bb;
                rowmax = fmaxf(rowmax, bb);
            }
            if (rowmax > 25.0f)                           // essentially never
                env_fallback8(cb, (k << 5) + r, tile0 + c0, best);
            macc = fmaxf(macc, rowmax);

            const float* op = out + ((size_t)((b * 2 + 1) * HH + (k << 5) + r)) * WW
                                  + tile0 + c0;
            float4 s0 = *(const float4*)op;
            float4 s1 = *(const float4*)(op + 4);
            float sv[8] = {s0.x, s0.y, s0.z, s0.w, s1.x, s1.y, s1.z, s1.w};
            #pragma unroll
            for (int i = 0; i < 8; ++i) {
                float gtv = (float)((gw[i] >> r) & 1u);   // gt float == gt bit
                float d = sv[i] - gtv;
                vacc += d * d * best[i];
            }
        }
        __syncthreads();   // protect s[] reuse by next tile
    }

    // ---- block reduce (8 warps), once per block ----
    int w  = t >> 5;
    int tc = t & 31;
    #pragma unroll
    for (int ofs = 16; ofs > 0; ofs >>= 1)
        vacc += __shfl_xor_sync(0xffffffffu, vacc, ofs);
    macc = redux_max_f32nn(macc);
    if (tc == 0) { red[0][w] = vacc; red[1][w] = macc; }
    __syncthreads();
    if (t == 0) {
        float x = ((red[0][0] + red[0][1]) + (red[0][2] + red[0][3]))
                + ((red[0][4] + red[0][5]) + (red[0][6] + red[0][7]));
        float y = fmaxf(fmaxf(fmaxf(red[1][0], red[1][1]), fmaxf(red[1][2], red[1][3])),
                        fmaxf(fmaxf(red[1][4], red[1][5]), fmaxf(red[1][6], red[1][7])));
        g_blksum[bi] = x;
        atomicMax(&g_maxbits[mb], __float_as_uint(y));
    }

    // ---- last-block finalize ----
    __threadfence();
    if (t == 0) amLast = (atomicAdd(&g_counter, 1u) == NBLK - 1);
    __syncthreads();
    if (!amLast) return;

    if (t < 128) {
        int wq = t >> 5, lq = t & 31;     // 4 warps x 4 groups each
        #pragma unroll
        for (int q = 0; q < 4; ++q) {
            int g = (wq << 2) + q;        // group = mb; 32 partials each
            double acc = (double)g_blksum[g * 32 + lq];
            #pragma unroll
            for (int ofs = 16; ofs > 0; ofs >>= 1)
                acc += __shfl_xor_sync(0xffffffffu, acc, ofs);
            if (lq == 0) {
                double mx = (double)fmaxf(__uint_as_float(g_maxbits[g]), 1.0f);
                part[g] = acc / mx;
            }
        }
    }
    __syncthreads();
    if (t == 0) {
        double total = 0.0;
        #pragma unroll
        for (int q = 0; q < 16; ++q) total += part[q];
        res[0] = (float)(total * (1.0 / (double)NPIX));
        g_counter = 0;                    // reset for next replay
    }
}

extern "C" void kernel_launch(void* const* d_in, const int* in_sizes, int n_in,
                              void* d_out, int out_size) {
    const float* out = (const float*)d_in[0];   // [8,2,512,512] float32
    const int*   tgt = (const int*)d_in[1];     // [8,1,512,512] int32

    k_bits<<<NGRP * KW, 256>>>(out, tgt);       // 256 blocks
    k_band<<<NBLK, TPB>>>(out, (float*)d_out);
}